// round 9
// baseline (speedup 1.0000x reference)
#include <cuda_runtime.h>
#include <math.h>
#include <stdint.h>

#define NROWS 8192
#define NCOLS 8192
#define W     2048              // cols per block tile
#define R     32                // rows per block tile
#define CHR   4                 // rows per chunk
#define NCH   (R / CHR)         // 8 chunks per block
#define S     3                 // pipeline stages
#define GX    (NCOLS / W)       // 4
#define GY    (NROWS / R)       // 256
#define NBLK  (GX * GY)         // 1024
#define STAGE_FLOATS (CHR * W)  // 8192 floats = 32KB per stage
#define DYN_SMEM (S * STAGE_FLOATS * 4)   // 96KB

// Scratch state. Invariant: all-zero at entry; last block restores zeros.
__device__ float g_rowsum[NROWS];
__device__ float g_colsum[NCOLS];
__device__ float g_s1part[NBLK];
__device__ unsigned int g_count;

__device__ __forceinline__ void cp16(uint32_t dst, const void* src) {
    asm volatile("cp.async.cg.shared.global [%0], [%1], 16;\n" :: "r"(dst), "l"(src));
}
__device__ __forceinline__ void cp_commit() {
    asm volatile("cp.async.commit_group;\n");
}
template <int N> __device__ __forceinline__ void cp_wait() {
    asm volatile("cp.async.wait_group %0;\n" :: "n"(N));
}

// Issue chunk c (4 rows x 2048 cols) into stage c%S. Each thread copies its
// own 8 x 16B slots; it is also the only consumer of those slots.
__device__ __forceinline__ void issue_chunk(const float* __restrict__ ct,
                                            uint32_t sbase, int c,
                                            int r0, int c0, int tid) {
    uint32_t st = sbase + (uint32_t)(c % S) * (STAGE_FLOATS * 4);
    const float* g = ct + (size_t)(r0 + c * CHR) * NCOLS + c0 + 4 * tid;
    #pragma unroll
    for (int j = 0; j < CHR; ++j) {
        #pragma unroll
        for (int p = 0; p < 2; ++p) {
            uint32_t dst = st + (uint32_t)(j * (W / 4) + tid + 256 * p) * 16u;
            cp16(dst, g + (size_t)j * NCOLS + 1024 * p);
        }
    }
    cp_commit();
}

__global__ __launch_bounds__(256) void mi_fused_kernel(const float* __restrict__ ct,
                                                       float* __restrict__ out) {
    extern __shared__ float stg[];        // [S][STAGE_FLOATS]
    const int tid = threadIdx.x;
    const int w   = tid >> 5;
    const int l   = tid & 31;
    const int c0  = blockIdx.x * W;
    const int r0  = blockIdx.y * R;

    const uint32_t sbase = (uint32_t)__cvta_generic_to_shared(stg);

    __shared__ float sp[CHR][256];        // per-chunk row partials

    float ca[8];                          // col accumulators: col = c0 + 4*tid + 1024*p + m
    #pragma unroll
    for (int i = 0; i < 8; ++i) ca[i] = 0.f;
    float s1a = 0.f, s1b = 0.f, s1c = 0.f, s1d = 0.f;

    // prologue: fill S-1 stages
    #pragma unroll
    for (int c = 0; c < S - 1; ++c)
        issue_chunk(ct, sbase, c, r0, c0, tid);

    for (int c = 0; c < NCH; ++c) {
        cp_wait<S - 2>();                 // own-thread slots of chunk c are in SMEM

        const float4* buf =
            reinterpret_cast<const float4*>(stg + (size_t)(c % S) * STAGE_FLOATS);

        float rp[CHR];
        #pragma unroll
        for (int j = 0; j < CHR; ++j) rp[j] = 0.f;

        #pragma unroll
        for (int j = 0; j < CHR; ++j) {
            #pragma unroll
            for (int p = 0; p < 2; ++p) {
                float4 v = buf[j * (W / 4) + tid + 256 * p];
                float x = v.x, y = v.y, z = v.z, q = v.w;
                // inputs >= 0; nonzero values >= 2^-24 so fmaxf(v,1e-30) == v,
                // and v==0 contributes 0 * log2(1e-30) = 0.
                s1a = __fmaf_rn(x, __log2f(fmaxf(x, 1e-30f)), s1a);
                s1b = __fmaf_rn(y, __log2f(fmaxf(y, 1e-30f)), s1b);
                s1c = __fmaf_rn(z, __log2f(fmaxf(z, 1e-30f)), s1c);
                s1d = __fmaf_rn(q, __log2f(fmaxf(q, 1e-30f)), s1d);
                ca[p * 4 + 0] += x; ca[p * 4 + 1] += y;
                ca[p * 4 + 2] += z; ca[p * 4 + 3] += q;
                rp[j] += (x + y) + (z + q);
            }
        }

        // row reduction for this chunk's 4 rows (outside the copy path)
        #pragma unroll
        for (int j = 0; j < CHR; ++j) sp[j][tid] = rp[j];
        __syncthreads();
        if (w < CHR) {
            float t = 0.f;
            #pragma unroll
            for (int k = 0; k < 8; ++k) t += sp[w][l + 32 * k];
            #pragma unroll
            for (int o = 16; o > 0; o >>= 1)
                t += __shfl_xor_sync(0xffffffffu, t, o);
            if (l == 0) atomicAdd(&g_rowsum[r0 + c * CHR + w], t);
        }
        __syncthreads();                  // scratch + stage safe to reuse

        if (c + S - 1 < NCH)
            issue_chunk(ct, sbase, c + S - 1, r0, c0, tid);
    }

    // ---- column sums: thread owns 8 fixed cols -> direct atomics ----
    #pragma unroll
    for (int p = 0; p < 2; ++p)
        #pragma unroll
        for (int m = 0; m < 4; ++m)
            atomicAdd(&g_colsum[c0 + 4 * tid + 1024 * p + m], ca[p * 4 + m]);

    // ---- S1 block partial -> plain store ----
    {
        float s1 = (s1a + s1b) + (s1c + s1d);
        #pragma unroll
        for (int o = 16; o > 0; o >>= 1)
            s1 += __shfl_xor_sync(0xffffffffu, s1, o);
        __shared__ float sw[8];
        if (l == 0) sw[w] = s1;
        __syncthreads();
        if (tid == 0) {
            float t = 0.f;
            #pragma unroll
            for (int k = 0; k < 8; ++k) t += sw[k];
            g_s1part[blockIdx.y * gridDim.x + blockIdx.x] = t;
        }
    }

    // ---- last-block completion ----
    __shared__ unsigned int is_last;
    __threadfence();
    __syncthreads();
    if (tid == 0) {
        unsigned int old = atomicAdd(&g_count, 1u);
        is_last = (old == (unsigned int)(NBLK - 1)) ? 1u : 0u;
    }
    __syncthreads();
    if (!is_last) return;

    __threadfence();  // acquire: see all blocks' writes

    double acc = 0.0;
    for (int i = tid; i < NROWS; i += 256) {
        float s = g_rowsum[i];
        if (s > 0.f) acc -= (double)s * (double)__log2f(s);
        g_rowsum[i] = 0.0f;
    }
    for (int i = tid; i < NCOLS; i += 256) {
        float s = g_colsum[i];
        if (s > 0.f) acc -= (double)s * (double)__log2f(s);
        g_colsum[i] = 0.0f;
    }
    for (int i = tid; i < NBLK; i += 256)
        acc += (double)g_s1part[i];

    #pragma unroll
    for (int o = 16; o > 0; o >>= 1)
        acc += __shfl_xor_sync(0xffffffffu, acc, o);
    __shared__ double sd[8];
    if (l == 0) sd[w] = acc;
    __syncthreads();
    if (tid == 0) {
        double a = 0.0;
        #pragma unroll
        for (int k = 0; k < 8; ++k) a += sd[k];
        out[0] = (float)a;
        g_count = 0u;
    }
}

extern "C" void kernel_launch(void* const* d_in, const int* in_sizes, int n_in,
                              void* d_out, int out_size) {
    const float* ct = (const float*)d_in[0];
    float* out = (float*)d_out;

    // Idempotent, not a stream op: safe under graph capture.
    cudaFuncSetAttribute(mi_fused_kernel,
                         cudaFuncAttributeMaxDynamicSharedMemorySize, DYN_SMEM);

    dim3 grid(GX, GY);
    mi_fused_kernel<<<grid, 256, DYN_SMEM>>>(ct, out);
}